// round 1
// baseline (speedup 1.0000x reference)
#include <cuda_runtime.h>

// ---------------------------------------------------------------------------
// AxialAttention: B=2, S=2048, E=1024, H=16, D=64
//
// Algorithm (after algebraic simplification of the reference):
//   Qf = X @ Wq^T + bq          [4096,1024]   (X = query flattened [B*S, E])
//   Kf = X @ Wk^T + bk
//   Vf = X @ Wv^T + bv
//   S[b] = Qf[b] @ Kf[b]^T / 128               (mean-over-heads folds into /H*sqrt(d))
//   P[b] = softmax_rows(S[b])
//   Y[b] = P[b] @ Vf[b], stored SHUFFLED: (q, e=h*64+d) -> (h*128+q/16, (q%16)*64+d)
//   out  = Yshuf @ Wo^T + bo
// ---------------------------------------------------------------------------

#define BM 128
#define BN 128
#define BK 16

// scratch (allocated at module load, not inside kernel_launch)
__device__ float g_Q[2 * 2048 * 1024];
__device__ float g_K[2 * 2048 * 1024];
__device__ float g_V[2 * 2048 * 1024];
__device__ float g_S[2 * 2048 * 2048];
__device__ float g_Y[2 * 2048 * 1024];

// ---------------------------------------------------------------------------
// C = alpha * (A @ B^T) [+ bias], A [M,K] row-major, B [N,K] row-major.
// Batched via blockIdx.z with element strides sA/sB/sC.
// 256 threads, 128x128 block tile, 8x8 per-thread microtile (split 4+64).
// ---------------------------------------------------------------------------
__global__ __launch_bounds__(256) void gemm_nt(
    const float* __restrict__ A, const float* __restrict__ B,
    const float* __restrict__ bias, float* __restrict__ C,
    int M, int N, int K, float alpha,
    long long sA, long long sB, long long sC)
{
    __shared__ float As[BK][BM + 4];
    __shared__ float Bs[BK][BN + 4];

    const float* Ab = A + blockIdx.z * sA + (long long)blockIdx.y * BM * K;
    const float* Bb = B + blockIdx.z * sB + (long long)blockIdx.x * BN * K;
    float* Cb = C + blockIdx.z * sC;

    int tid = threadIdx.x;
    int tx = tid & 15;      // 0..15  (N direction)
    int ty = tid >> 4;      // 0..15  (M direction)
    int lrow = tid >> 2;            // 0..63
    int lcol = (tid & 3) << 2;      // 0,4,8,12

    float acc[8][8];
#pragma unroll
    for (int i = 0; i < 8; i++)
#pragma unroll
        for (int j = 0; j < 8; j++) acc[i][j] = 0.f;

    for (int k0 = 0; k0 < K; k0 += BK) {
#pragma unroll
        for (int p = 0; p < 2; p++) {
            int r = lrow + p * 64;
            float4 va = *(const float4*)(Ab + (long long)r * K + k0 + lcol);
            As[lcol + 0][r] = va.x; As[lcol + 1][r] = va.y;
            As[lcol + 2][r] = va.z; As[lcol + 3][r] = va.w;
            float4 vb = *(const float4*)(Bb + (long long)r * K + k0 + lcol);
            Bs[lcol + 0][r] = vb.x; Bs[lcol + 1][r] = vb.y;
            Bs[lcol + 2][r] = vb.z; Bs[lcol + 3][r] = vb.w;
        }
        __syncthreads();
#pragma unroll
        for (int kk = 0; kk < BK; kk++) {
            float4 a0 = *(const float4*)&As[kk][ty * 4];
            float4 a1 = *(const float4*)&As[kk][ty * 4 + 64];
            float4 b0 = *(const float4*)&Bs[kk][tx * 4];
            float4 b1 = *(const float4*)&Bs[kk][tx * 4 + 64];
            float a[8] = {a0.x, a0.y, a0.z, a0.w, a1.x, a1.y, a1.z, a1.w};
            float b[8] = {b0.x, b0.y, b0.z, b0.w, b1.x, b1.y, b1.z, b1.w};
#pragma unroll
            for (int i = 0; i < 8; i++)
#pragma unroll
                for (int j = 0; j < 8; j++)
                    acc[i][j] = fmaf(a[i], b[j], acc[i][j]);
        }
        __syncthreads();
    }

#pragma unroll
    for (int i = 0; i < 8; i++) {
        int row = blockIdx.y * BM + ty * 4 + (i & 3) + ((i >> 2) * 64);
#pragma unroll
        for (int jj = 0; jj < 2; jj++) {
            int col = blockIdx.x * BN + tx * 4 + jj * 64;
            float4 o;
            o.x = acc[i][jj * 4 + 0] * alpha;
            o.y = acc[i][jj * 4 + 1] * alpha;
            o.z = acc[i][jj * 4 + 2] * alpha;
            o.w = acc[i][jj * 4 + 3] * alpha;
            if (bias) {
                o.x += bias[col + 0]; o.y += bias[col + 1];
                o.z += bias[col + 2]; o.w += bias[col + 3];
            }
            *(float4*)(Cb + (long long)row * N + col) = o;
        }
    }
}

// ---------------------------------------------------------------------------
// C = A @ B with SHUFFLED store. A [M,K] row-major (softmax weights),
// B [K,N] row-major (Vf). Element (q,e) of Y goes to
//   srow = (e>>6)*128 + (q>>4),  scol = ((q&15)<<6) + (e&63)   (row len 1024)
// ---------------------------------------------------------------------------
__global__ __launch_bounds__(256) void gemm_nn_shuffle(
    const float* __restrict__ A, const float* __restrict__ B,
    float* __restrict__ C,
    int M, int N, int K,
    long long sA, long long sB, long long sC)
{
    __shared__ float As[BK][BM + 4];
    __shared__ float Bs[BK][BN + 4];

    const float* Ab = A + blockIdx.z * sA + (long long)blockIdx.y * BM * K;
    const float* Bb = B + blockIdx.z * sB;
    float* Cb = C + blockIdx.z * sC;

    int tid = threadIdx.x;
    int tx = tid & 15;
    int ty = tid >> 4;
    int larow = tid >> 2;
    int lacol = (tid & 3) << 2;
    int bcol = (tid & 31) << 2;   // 0..124
    int brow = tid >> 5;          // 0..7

    float acc[8][8];
#pragma unroll
    for (int i = 0; i < 8; i++)
#pragma unroll
        for (int j = 0; j < 8; j++) acc[i][j] = 0.f;

    for (int k0 = 0; k0 < K; k0 += BK) {
#pragma unroll
        for (int p = 0; p < 2; p++) {
            int r = larow + p * 64;
            float4 va = *(const float4*)(Ab + (long long)r * K + k0 + lacol);
            As[lacol + 0][r] = va.x; As[lacol + 1][r] = va.y;
            As[lacol + 2][r] = va.z; As[lacol + 3][r] = va.w;
            int kr = brow + p * 8;
            float4 vb = *(const float4*)(Bb + (long long)(k0 + kr) * N +
                                         blockIdx.x * BN + bcol);
            *(float4*)&Bs[kr][bcol] = vb;
        }
        __syncthreads();
#pragma unroll
        for (int kk = 0; kk < BK; kk++) {
            float4 a0 = *(const float4*)&As[kk][ty * 4];
            float4 a1 = *(const float4*)&As[kk][ty * 4 + 64];
            float4 b0 = *(const float4*)&Bs[kk][tx * 4];
            float4 b1 = *(const float4*)&Bs[kk][tx * 4 + 64];
            float a[8] = {a0.x, a0.y, a0.z, a0.w, a1.x, a1.y, a1.z, a1.w};
            float b[8] = {b0.x, b0.y, b0.z, b0.w, b1.x, b1.y, b1.z, b1.w};
#pragma unroll
            for (int i = 0; i < 8; i++)
#pragma unroll
                for (int j = 0; j < 8; j++)
                    acc[i][j] = fmaf(a[i], b[j], acc[i][j]);
        }
        __syncthreads();
    }

#pragma unroll
    for (int i = 0; i < 8; i++) {
        int q = blockIdx.y * BM + ty * 4 + (i & 3) + ((i >> 2) * 64);
#pragma unroll
        for (int j = 0; j < 8; j++) {
            int e = blockIdx.x * BN + tx * 4 + (j & 3) + ((j >> 2) * 64);
            int h = e >> 6, d = e & 63;
            int srow = h * 128 + (q >> 4);
            int scol = ((q & 15) << 6) + d;
            Cb[(long long)srow * 1024 + scol] = acc[i][j];
        }
    }
}

// ---------------------------------------------------------------------------
// In-place row softmax, row length 2048, one block of 256 threads per row.
// ---------------------------------------------------------------------------
__global__ __launch_bounds__(256) void softmax2048(float* __restrict__ S)
{
    float* row = S + (long long)blockIdx.x * 2048;
    int tid = threadIdx.x;
    float4 v0 = ((const float4*)row)[tid];
    float4 v1 = ((const float4*)row)[tid + 256];

    float m = fmaxf(fmaxf(fmaxf(v0.x, v0.y), fmaxf(v0.z, v0.w)),
                    fmaxf(fmaxf(v1.x, v1.y), fmaxf(v1.z, v1.w)));
#pragma unroll
    for (int o = 16; o; o >>= 1) m = fmaxf(m, __shfl_xor_sync(0xffffffffu, m, o));

    __shared__ float sm[8], ss[8];
    int w = tid >> 5, lane = tid & 31;
    if (lane == 0) sm[w] = m;
    __syncthreads();
    m = sm[0];
#pragma unroll
    for (int i = 1; i < 8; i++) m = fmaxf(m, sm[i]);

    v0.x = __expf(v0.x - m); v0.y = __expf(v0.y - m);
    v0.z = __expf(v0.z - m); v0.w = __expf(v0.w - m);
    v1.x = __expf(v1.x - m); v1.y = __expf(v1.y - m);
    v1.z = __expf(v1.z - m); v1.w = __expf(v1.w - m);

    float s = v0.x + v0.y + v0.z + v0.w + v1.x + v1.y + v1.z + v1.w;
#pragma unroll
    for (int o = 16; o; o >>= 1) s += __shfl_xor_sync(0xffffffffu, s, o);
    if (lane == 0) ss[w] = s;
    __syncthreads();
    s = ss[0] + ss[1] + ss[2] + ss[3] + ss[4] + ss[5] + ss[6] + ss[7];
    float inv = 1.0f / s;

    v0.x *= inv; v0.y *= inv; v0.z *= inv; v0.w *= inv;
    v1.x *= inv; v1.y *= inv; v1.z *= inv; v1.w *= inv;
    ((float4*)row)[tid] = v0;
    ((float4*)row)[tid + 256] = v1;
}

// ---------------------------------------------------------------------------
extern "C" void kernel_launch(void* const* d_in, const int* in_sizes, int n_in,
                              void* d_out, int out_size)
{
    const float* x  = (const float*)d_in[0];
    const float* Wq = (const float*)d_in[1];
    const float* bq = (const float*)d_in[2];
    const float* Wk = (const float*)d_in[3];
    const float* bk = (const float*)d_in[4];
    const float* Wv = (const float*)d_in[5];
    const float* bv = (const float*)d_in[6];
    const float* Wo = (const float*)d_in[7];
    const float* bo = (const float*)d_in[8];
    float* out = (float*)d_out;

    float *Q, *K, *V, *S, *Y;
    cudaGetSymbolAddress((void**)&Q, g_Q);
    cudaGetSymbolAddress((void**)&K, g_K);
    cudaGetSymbolAddress((void**)&V, g_V);
    cudaGetSymbolAddress((void**)&S, g_S);
    cudaGetSymbolAddress((void**)&Y, g_Y);

    dim3 blk(256);

    // QKV projections: [4096,1024] = X @ W^T + b
    gemm_nt<<<dim3(8, 32, 1), blk>>>(x, Wq, bq, Q, 4096, 1024, 1024, 1.f, 0, 0, 0);
    gemm_nt<<<dim3(8, 32, 1), blk>>>(x, Wk, bk, K, 4096, 1024, 1024, 1.f, 0, 0, 0);
    gemm_nt<<<dim3(8, 32, 1), blk>>>(x, Wv, bv, V, 4096, 1024, 1024, 1.f, 0, 0, 0);

    // scores = Qf @ Kf^T / 128 per batch  -> [2,2048,2048]
    gemm_nt<<<dim3(16, 16, 2), blk>>>(Q, K, nullptr, S, 2048, 2048, 1024,
                                      1.f / 128.f,
                                      2048ll * 1024, 2048ll * 1024, 2048ll * 2048);

    // softmax over last dim (4096 rows of 2048)
    softmax2048<<<4096, 256>>>(S);

    // Y = P @ Vf per batch, stored with the reference's no-transpose reshape shuffle
    gemm_nn_shuffle<<<dim3(8, 16, 2), blk>>>(S, V, Y, 2048, 1024, 2048,
                                             2048ll * 2048, 2048ll * 1024,
                                             2048ll * 1024);

    // out = Yshuf @ Wo^T + bo
    gemm_nt<<<dim3(8, 32, 1), blk>>>(Y, Wo, bo, out, 4096, 1024, 1024, 1.f, 0, 0, 0);
}

// round 3
// speedup vs baseline: 2.8902x; 2.8902x over previous
#include <cuda_runtime.h>
#include <cstdint>

// ===========================================================================
// AxialAttention via mma.sync tf32 (sm_103-portable tensor path).
//   Qf = Xr@Wqr^T+bq ; Kf = Xr@Wkr^T+bk       [4096,1024]   (r = tf32-rounded)
//   Vt = Wvr@Xr^T+bv  stored [1024,4096]  (col s = b*2048+q)
//   S  = Q@K^T / 128 per batch ; P = softmax rows (rounded)
//   Y  = P@Vt^T per batch, stored with reference's no-transpose reshape shuffle
//   out= Y@Wor^T + bo
// All GEMMs NT: A [M,K] lda, B [N,K] ldb, both K-major.
// ===========================================================================

#define BK 32
#define STRIDE 36                      // BK + 4 pad floats
#define STG_FLOATS (128 * STRIDE)
#define STG_BYTES (STG_FLOATS * 4)     // 18432
#define STAGES 3
#define SMEM_TOT (2 * STAGES * STG_BYTES)  // 110592

// scratch
__device__ float g_Xr[4096 * 1024];
__device__ float g_Wr[4 * 1024 * 1024];     // Wq, Wk, Wv, Wo rounded
__device__ float g_Q [4096 * 1024];
__device__ float g_K [4096 * 1024];
__device__ float g_Vt[1024 * 4096];
__device__ float g_S [2ll * 2048 * 2048];
__device__ float g_Y [4096 * 1024];

__device__ __forceinline__ float rtf32(float x) {
    uint32_t u;
    asm("cvt.rna.tf32.f32 %0, %1;" : "=r"(u) : "f"(x));
    return __uint_as_float(u);
}

__device__ __forceinline__ void mma_tf32(float* d, const uint32_t* a, const uint32_t* b) {
    asm volatile(
        "mma.sync.aligned.m16n8k8.row.col.f32.tf32.tf32.f32 "
        "{%0,%1,%2,%3}, {%4,%5,%6,%7}, {%8,%9}, {%0,%1,%2,%3};"
        : "+f"(d[0]), "+f"(d[1]), "+f"(d[2]), "+f"(d[3])
        : "r"(a[0]), "r"(a[1]), "r"(a[2]), "r"(a[3]), "r"(b[0]), "r"(b[1]));
}

#define CP_ASYNC(dst, src) \
    asm volatile("cp.async.cg.shared.global [%0], [%1], 16;" :: "r"(dst), \
                 "l"(__cvta_generic_to_global(src)))
#define CP_COMMIT() asm volatile("cp.async.commit_group;" ::: "memory")
#define CP_WAIT1()  asm volatile("cp.async.wait_group 1;" ::: "memory")

// ---------------------------------------------------------------------------
// MODE 0: plain store, bias by column. MODE 1: plain store, bias by row.
// MODE 2: shuffle store (reference's no-transpose reshape), no bias.
// ---------------------------------------------------------------------------
template <int MODE>
__global__ void __launch_bounds__(256, 1) mma_gemm(
    const float* __restrict__ A, int lda, long long sA,
    const float* __restrict__ B, int ldb, long long sB,
    const float* __restrict__ bias,
    float* __restrict__ C, int ldC, long long sC,
    int nch, float alpha, int rnd)
{
    extern __shared__ __align__(16) char smc[];
    float* Abase = (float*)smc;
    float* Bbase = (float*)(smc + STAGES * STG_BYTES);

    const float* Ab = A + blockIdx.z * sA + (long long)blockIdx.y * 128 * lda;
    const float* Bb = B + blockIdx.z * sB + (long long)blockIdx.x * 128 * ldb;

    int tid = threadIdx.x, lane = tid & 31, wid = tid >> 5;
    int gr = lane >> 2, qc = lane & 3;
    int mw = (wid >> 2) * 64, nw = (wid & 3) * 32;

    uint32_t sA32 = (uint32_t)__cvta_generic_to_shared(Abase);
    uint32_t sB32 = (uint32_t)__cvta_generic_to_shared(Bbase);
    int lr = tid >> 3;            // 0..31
    int lc = (tid & 7) * 4;       // 0..28

    float acc[4][4][4];
#pragma unroll
    for (int i = 0; i < 4; i++)
#pragma unroll
        for (int j = 0; j < 4; j++)
#pragma unroll
            for (int t = 0; t < 4; t++) acc[i][j][t] = 0.f;

    auto load_stage = [&](int ch, int st) {
        long long ko = (long long)ch * BK + lc;
#pragma unroll
        for (int it = 0; it < 4; it++) {
            int r = it * 32 + lr;
            uint32_t so = (uint32_t)(st * STG_BYTES + (r * STRIDE + lc) * 4);
            CP_ASYNC(sA32 + so, Ab + (long long)r * lda + ko);
            CP_ASYNC(sB32 + so, Bb + (long long)r * ldb + ko);
        }
    };

    load_stage(0, 0);
    CP_COMMIT();
    load_stage(1, 1);
    CP_COMMIT();

    for (int ch = 0; ch < nch; ch++) {
        CP_WAIT1();
        __syncthreads();
        if (ch + 2 < nch) load_stage(ch + 2, (ch + 2) % STAGES);
        CP_COMMIT();

        const float* As = Abase + (ch % STAGES) * STG_FLOATS;
        const float* Bs = Bbase + (ch % STAGES) * STG_FLOATS;
#pragma unroll
        for (int kk = 0; kk < BK; kk += 8) {
            uint32_t af[4][4], bf[4][2];
#pragma unroll
            for (int mf = 0; mf < 4; mf++) {
                const float* p = As + (mw + mf * 16 + gr) * STRIDE + kk + qc;
                af[mf][0] = __float_as_uint(p[0]);
                af[mf][1] = __float_as_uint(p[8 * STRIDE]);
                af[mf][2] = __float_as_uint(p[4]);
                af[mf][3] = __float_as_uint(p[8 * STRIDE + 4]);
            }
#pragma unroll
            for (int nf = 0; nf < 4; nf++) {
                const float* p = Bs + (nw + nf * 8 + gr) * STRIDE + kk + qc;
                bf[nf][0] = __float_as_uint(p[0]);
                bf[nf][1] = __float_as_uint(p[4]);
            }
#pragma unroll
            for (int mf = 0; mf < 4; mf++)
#pragma unroll
                for (int nf = 0; nf < 4; nf++)
                    mma_tf32(acc[mf][nf], af[mf], bf[nf]);
        }
    }

    // epilogue
    float* Cb = C + blockIdx.z * sC;
#pragma unroll
    for (int mf = 0; mf < 4; mf++) {
#pragma unroll
        for (int nf = 0; nf < 4; nf++) {
            int row = blockIdx.y * 128 + mw + mf * 16 + gr;
            int col = blockIdx.x * 128 + nw + nf * 8 + 2 * qc;
            float v0 = acc[mf][nf][0] * alpha;
            float v1 = acc[mf][nf][1] * alpha;
            float v2 = acc[mf][nf][2] * alpha;
            float v3 = acc[mf][nf][3] * alpha;
            if (MODE == 0 && bias) {
                float b0 = bias[col], b1 = bias[col + 1];
                v0 += b0; v1 += b1; v2 += b0; v3 += b1;
            }
            if (MODE == 1) {
                float b0 = bias[row], b1 = bias[row + 8];
                v0 += b0; v1 += b0; v2 += b1; v3 += b1;
            }
            if (rnd) {
                v0 = rtf32(v0); v1 = rtf32(v1);
                v2 = rtf32(v2); v3 = rtf32(v3);
            }
            if (MODE == 2) {
                int h = col >> 6, d0 = col & 63;
                long long o0 = (long long)(h * 128 + (row >> 4)) * 1024 +
                               ((row & 15) << 6) + d0;
                int row2 = row + 8;
                long long o1 = (long long)(h * 128 + (row2 >> 4)) * 1024 +
                               ((row2 & 15) << 6) + d0;
                *(float2*)(Cb + o0) = make_float2(v0, v1);
                *(float2*)(Cb + o1) = make_float2(v2, v3);
            } else {
                *(float2*)(Cb + (long long)row * ldC + col) = make_float2(v0, v1);
                *(float2*)(Cb + (long long)(row + 8) * ldC + col) = make_float2(v2, v3);
            }
        }
    }
}

// ---------------------------------------------------------------------------
__global__ __launch_bounds__(256) void round_copy(const float4* __restrict__ in,
                                                  float4* __restrict__ out, int n4)
{
    int i = blockIdx.x * 256 + threadIdx.x;
    if (i < n4) {
        float4 v = in[i];
        v.x = rtf32(v.x); v.y = rtf32(v.y); v.z = rtf32(v.z); v.w = rtf32(v.w);
        out[i] = v;
    }
}

// ---------------------------------------------------------------------------
// row softmax (2048 wide), output rounded to tf32 grid
// ---------------------------------------------------------------------------
__global__ __launch_bounds__(256) void softmax2048(float* __restrict__ S)
{
    float* row = S + (long long)blockIdx.x * 2048;
    int tid = threadIdx.x;
    float4 v0 = ((const float4*)row)[tid];
    float4 v1 = ((const float4*)row)[tid + 256];

    float m = fmaxf(fmaxf(fmaxf(v0.x, v0.y), fmaxf(v0.z, v0.w)),
                    fmaxf(fmaxf(v1.x, v1.y), fmaxf(v1.z, v1.w)));
#pragma unroll
    for (int o = 16; o; o >>= 1) m = fmaxf(m, __shfl_xor_sync(0xffffffffu, m, o));

    __shared__ float sm[8], ss[8];
    int w = tid >> 5, lane = tid & 31;
    if (lane == 0) sm[w] = m;
    __syncthreads();
    m = sm[0];
#pragma unroll
    for (int i = 1; i < 8; i++) m = fmaxf(m, sm[i]);

    v0.x = __expf(v0.x - m); v0.y = __expf(v0.y - m);
    v0.z = __expf(v0.z - m); v0.w = __expf(v0.w - m);
    v1.x = __expf(v1.x - m); v1.y = __expf(v1.y - m);
    v1.z = __expf(v1.z - m); v1.w = __expf(v1.w - m);

    float s = v0.x + v0.y + v0.z + v0.w + v1.x + v1.y + v1.z + v1.w;
#pragma unroll
    for (int o = 16; o; o >>= 1) s += __shfl_xor_sync(0xffffffffu, s, o);
    if (lane == 0) ss[w] = s;
    __syncthreads();
    s = ss[0] + ss[1] + ss[2] + ss[3] + ss[4] + ss[5] + ss[6] + ss[7];
    float inv = 1.0f / s;

    v0.x = rtf32(v0.x * inv); v0.y = rtf32(v0.y * inv);
    v0.z = rtf32(v0.z * inv); v0.w = rtf32(v0.w * inv);
    v1.x = rtf32(v1.x * inv); v1.y = rtf32(v1.y * inv);
    v1.z = rtf32(v1.z * inv); v1.w = rtf32(v1.w * inv);
    ((float4*)row)[tid] = v0;
    ((float4*)row)[tid + 256] = v1;
}

// ---------------------------------------------------------------------------
extern "C" void kernel_launch(void* const* d_in, const int* in_sizes, int n_in,
                              void* d_out, int out_size)
{
    const float* x  = (const float*)d_in[0];
    const float* bq = (const float*)d_in[2];
    const float* bk = (const float*)d_in[4];
    const float* bv = (const float*)d_in[6];
    const float* bo = (const float*)d_in[8];
    float* out = (float*)d_out;

    float *Xr, *Wr, *Q, *K, *Vt, *S, *Y;
    cudaGetSymbolAddress((void**)&Xr, g_Xr);
    cudaGetSymbolAddress((void**)&Wr, g_Wr);
    cudaGetSymbolAddress((void**)&Q,  g_Q);
    cudaGetSymbolAddress((void**)&K,  g_K);
    cudaGetSymbolAddress((void**)&Vt, g_Vt);
    cudaGetSymbolAddress((void**)&S,  g_S);
    cudaGetSymbolAddress((void**)&Y,  g_Y);

    static int configured = 0;
    cudaFuncSetAttribute(mma_gemm<0>, cudaFuncAttributeMaxDynamicSharedMemorySize, SMEM_TOT);
    cudaFuncSetAttribute(mma_gemm<1>, cudaFuncAttributeMaxDynamicSharedMemorySize, SMEM_TOT);
    cudaFuncSetAttribute(mma_gemm<2>, cudaFuncAttributeMaxDynamicSharedMemorySize, SMEM_TOT);
    (void)configured;

    // pre-round inputs to tf32 grid (kills HMMA truncation bias)
    round_copy<<<4096, 256>>>((const float4*)x, (float4*)Xr, 1024 * 1024);
    round_copy<<<1024, 256>>>((const float4*)d_in[1], (float4*)(Wr + 0 * 1048576), 262144);
    round_copy<<<1024, 256>>>((const float4*)d_in[3], (float4*)(Wr + 1 * 1048576), 262144);
    round_copy<<<1024, 256>>>((const float4*)d_in[5], (float4*)(Wr + 2 * 1048576), 262144);
    round_copy<<<1024, 256>>>((const float4*)d_in[7], (float4*)(Wr + 3 * 1048576), 262144);

    dim3 blk(256);

    // Q = Xr @ Wq^T + bq  [4096,1024]   (rounded store)
    mma_gemm<0><<<dim3(8, 32, 1), blk, SMEM_TOT>>>(Xr, 1024, 0, Wr, 1024, 0,
                                                   bq, Q, 1024, 0, 32, 1.f, 1);
    // K
    mma_gemm<0><<<dim3(8, 32, 1), blk, SMEM_TOT>>>(Xr, 1024, 0, Wr + 1048576, 1024, 0,
                                                   bk, K, 1024, 0, 32, 1.f, 1);
    // Vt = Wv @ Xr^T + bv (bias by row=e)  [1024,4096]  (rounded)
    mma_gemm<1><<<dim3(32, 8, 1), blk, SMEM_TOT>>>(Wr + 2097152, 1024, 0, Xr, 1024, 0,
                                                   bv, Vt, 4096, 0, 32, 1.f, 1);
    // S = Q @ K^T / 128 per batch  [2,2048,2048]  (unrounded; softmax rounds)
    mma_gemm<0><<<dim3(16, 16, 2), blk, SMEM_TOT>>>(Q, 1024, 2048ll * 1024,
                                                    K, 1024, 2048ll * 1024,
                                                    nullptr, S, 2048, 2048ll * 2048,
                                                    32, 1.f / 128.f, 0);
    softmax2048<<<4096, 256>>>(S);
    // Y = P @ Vt^T per batch, shuffled store  (rounded)
    mma_gemm<2><<<dim3(8, 16, 2), blk, SMEM_TOT>>>(S, 2048, 2048ll * 2048,
                                                   Vt, 4096, 2048,
                                                   nullptr, Y, 1024, 2048ll * 1024,
                                                   64, 1.f, 1);
    // out = Y @ Wo^T + bo  (fp32 store)
    mma_gemm<0><<<dim3(8, 32, 1), blk, SMEM_TOT>>>(Y, 1024, 0, Wr + 3145728, 1024, 0,
                                                   bo, out, 1024, 0, 32, 1.f, 0);
}

// round 4
// speedup vs baseline: 6.1020x; 2.1112x over previous
#include <cuda_runtime.h>
#include <cuda_fp16.h>
#include <cstdint>

// ===========================================================================
// AxialAttention via mma.sync fp16 m16n8k16 (fp32 accum).
// fp16 mantissa == tf32 mantissa (10 bits) -> same accuracy, 2x rate, 1/2 traffic.
//   Qh = Xh@Wqh^T+bq ; Kh = Xh@Wkh^T+bk       [4096,1024] fp16
//   Vth = Wvh@Xh^T+bv  stored [1024,4096] fp16
//   Sf  = Qh@Kh^T / 128 per batch (fp32) ; Ph = softmax rows (fp16)
//   Yh  = Ph@Vth^T per batch, shuffle-stored (reference no-transpose reshape)
//   out = Yh@Woh^T + bo (fp32)
// All GEMMs NT: A [M,K] lda, B [N,K] ldb, both K-major, fp16.
// ===========================================================================

#define BK 64                         // fp16 elems per K-chunk (128 B per row)
#define ROW_BYTES 128
#define STG_BYTES (128 * ROW_BYTES)   // 16 KB
#define STAGES 3
#define SMEM_TOT (2 * STAGES * STG_BYTES)  // 96 KB

// scratch
__device__ __half g_Xh[4096 * 1024];
__device__ __half g_Wh[4 * 1024 * 1024];   // Wq,Wk,Wv,Wo fp16
__device__ __half g_Qh[4096 * 1024];
__device__ __half g_Kh[4096 * 1024];
__device__ __half g_Vt[1024 * 4096];
__device__ float  g_S [2ll * 2048 * 2048];
__device__ __half g_P [2ll * 2048 * 2048];
__device__ __half g_Y [4096 * 1024];

__device__ __forceinline__ void mma_f16(float* d, const uint32_t* a, const uint32_t* b) {
    asm volatile(
        "mma.sync.aligned.m16n8k16.row.col.f32.f16.f16.f32 "
        "{%0,%1,%2,%3}, {%4,%5,%6,%7}, {%8,%9}, {%0,%1,%2,%3};"
        : "+f"(d[0]), "+f"(d[1]), "+f"(d[2]), "+f"(d[3])
        : "r"(a[0]), "r"(a[1]), "r"(a[2]), "r"(a[3]), "r"(b[0]), "r"(b[1]));
}

#define CP_ASYNC(dst, src) \
    asm volatile("cp.async.cg.shared.global [%0], [%1], 16;" :: "r"(dst), \
                 "l"(__cvta_generic_to_global(src)))
#define CP_COMMIT() asm volatile("cp.async.commit_group;" ::: "memory")
#define CP_WAIT1()  asm volatile("cp.async.wait_group 1;" ::: "memory")

// ---------------------------------------------------------------------------
// MODE 0: plain store, bias by column. MODE 1: plain store, bias by row.
// MODE 2: shuffle store (reference's no-transpose reshape), no bias.
// HALF_OUT: store __half2, else float2.
// ---------------------------------------------------------------------------
template <int MODE, bool HALF_OUT>
__global__ void __launch_bounds__(256) mma_gemm(
    const __half* __restrict__ A, int lda, long long sA,
    const __half* __restrict__ B, int ldb, long long sB,
    const float* __restrict__ bias,
    void* __restrict__ Cv, int ldC, long long sC,
    int nch, float alpha)
{
    extern __shared__ __align__(128) char smc[];
    char* Abase = smc;
    char* Bbase = smc + STAGES * STG_BYTES;

    const __half* Ab = A + blockIdx.z * sA + (long long)blockIdx.y * 128 * lda;
    const __half* Bb = B + blockIdx.z * sB + (long long)blockIdx.x * 128 * ldb;

    int tid = threadIdx.x, lane = tid & 31, wid = tid >> 5;
    int gr = lane >> 2, qc = lane & 3;
    int mw = (wid >> 2) * 64, nw = (wid & 3) * 32;
    int q4 = qc * 4;

    uint32_t sA32 = (uint32_t)__cvta_generic_to_shared(Abase);
    uint32_t sB32 = (uint32_t)__cvta_generic_to_shared(Bbase);
    int lr = tid >> 3;            // 0..31
    int lc = tid & 7;             // 16B chunk 0..7

    float acc[4][4][4];
#pragma unroll
    for (int i = 0; i < 4; i++)
#pragma unroll
        for (int j = 0; j < 4; j++)
#pragma unroll
            for (int t = 0; t < 4; t++) acc[i][j][t] = 0.f;

    auto load_stage = [&](int ch, int st) {
        long long ko = (long long)ch * BK + lc * 8;
#pragma unroll
        for (int it = 0; it < 4; it++) {
            int r = it * 32 + lr;
            uint32_t so = (uint32_t)(st * STG_BYTES + r * ROW_BYTES +
                                     ((lc ^ (r & 7)) << 4));
            CP_ASYNC(sA32 + so, Ab + (long long)r * lda + ko);
            CP_ASYNC(sB32 + so, Bb + (long long)r * ldb + ko);
        }
    };

    load_stage(0, 0);
    CP_COMMIT();
    load_stage(1, 1);
    CP_COMMIT();

    for (int ch = 0; ch < nch; ch++) {
        CP_WAIT1();
        __syncthreads();
        if (ch + 2 < nch) load_stage(ch + 2, (ch + 2) % STAGES);
        CP_COMMIT();

        const char* As = Abase + (ch % STAGES) * STG_BYTES;
        const char* Bs = Bbase + (ch % STAGES) * STG_BYTES;
#pragma unroll
        for (int kk = 0; kk < BK; kk += 16) {
            int c0 = kk >> 3;                       // 16B chunk pair base
            uint32_t af[4][4], bf[4][2];
#pragma unroll
            for (int mf = 0; mf < 4; mf++) {
                const char* r0 = As + (mw + mf * 16 + gr) * ROW_BYTES;
                const char* r1 = r0 + 8 * ROW_BYTES;
                int s0 = ((c0 ^ gr) << 4) + q4;
                int s1 = (((c0 + 1) ^ gr) << 4) + q4;
                af[mf][0] = *(const uint32_t*)(r0 + s0);
                af[mf][1] = *(const uint32_t*)(r1 + s0);
                af[mf][2] = *(const uint32_t*)(r0 + s1);
                af[mf][3] = *(const uint32_t*)(r1 + s1);
            }
#pragma unroll
            for (int nf = 0; nf < 4; nf++) {
                const char* r0 = Bs + (nw + nf * 8 + gr) * ROW_BYTES;
                bf[nf][0] = *(const uint32_t*)(r0 + ((c0 ^ gr) << 4) + q4);
                bf[nf][1] = *(const uint32_t*)(r0 + (((c0 + 1) ^ gr) << 4) + q4);
            }
#pragma unroll
            for (int mf = 0; mf < 4; mf++)
#pragma unroll
                for (int nf = 0; nf < 4; nf++)
                    mma_f16(acc[mf][nf], af[mf], bf[nf]);
        }
    }

    // epilogue
#pragma unroll
    for (int mf = 0; mf < 4; mf++) {
#pragma unroll
        for (int nf = 0; nf < 4; nf++) {
            int row = blockIdx.y * 128 + mw + mf * 16 + gr;
            int col = blockIdx.x * 128 + nw + nf * 8 + 2 * qc;
            float v0 = acc[mf][nf][0] * alpha;
            float v1 = acc[mf][nf][1] * alpha;
            float v2 = acc[mf][nf][2] * alpha;
            float v3 = acc[mf][nf][3] * alpha;
            if (MODE == 0 && bias) {
                float b0 = bias[col], b1 = bias[col + 1];
                v0 += b0; v1 += b1; v2 += b0; v3 += b1;
            }
            if (MODE == 1) {
                float b0 = bias[row], b1 = bias[row + 8];
                v0 += b0; v1 += b0; v2 += b1; v3 += b1;
            }
            long long o0, o1;
            if (MODE == 2) {
                int h = col >> 6, d0 = col & 63;
                o0 = (long long)(h * 128 + (row >> 4)) * 1024 + ((row & 15) << 6) + d0;
                int row2 = row + 8;
                o1 = (long long)(h * 128 + (row2 >> 4)) * 1024 + ((row2 & 15) << 6) + d0;
            } else {
                o0 = (long long)row * ldC + col;
                o1 = o0 + 8ll * ldC;
            }
            if (HALF_OUT) {
                __half* Cb = (__half*)Cv + blockIdx.z * sC;
                *(__half2*)(Cb + o0) = __floats2half2_rn(v0, v1);
                *(__half2*)(Cb + o1) = __floats2half2_rn(v2, v3);
            } else {
                float* Cb = (float*)Cv + blockIdx.z * sC;
                *(float2*)(Cb + o0) = make_float2(v0, v1);
                *(float2*)(Cb + o1) = make_float2(v2, v3);
            }
        }
    }
}

// ---------------------------------------------------------------------------
__global__ __launch_bounds__(256) void f2h(const float4* __restrict__ in,
                                           __half* __restrict__ out, int n4)
{
    int i = blockIdx.x * 256 + threadIdx.x;
    if (i < n4) {
        float4 v = in[i];
        __half2 h0 = __floats2half2_rn(v.x, v.y);
        __half2 h1 = __floats2half2_rn(v.z, v.w);
        *(uint2*)(out + i * 4) = make_uint2(*(uint32_t*)&h0, *(uint32_t*)&h1);
    }
}

// ---------------------------------------------------------------------------
// row softmax on fp32 scores (2048 wide), fp16 output
// ---------------------------------------------------------------------------
__global__ __launch_bounds__(256) void softmax2048(const float* __restrict__ S,
                                                   __half* __restrict__ P)
{
    const float* row = S + (long long)blockIdx.x * 2048;
    __half* prow = P + (long long)blockIdx.x * 2048;
    int tid = threadIdx.x;
    float4 v0 = ((const float4*)row)[tid];
    float4 v1 = ((const float4*)row)[tid + 256];

    float m = fmaxf(fmaxf(fmaxf(v0.x, v0.y), fmaxf(v0.z, v0.w)),
                    fmaxf(fmaxf(v1.x, v1.y), fmaxf(v1.z, v1.w)));
#pragma unroll
    for (int o = 16; o; o >>= 1) m = fmaxf(m, __shfl_xor_sync(0xffffffffu, m, o));

    __shared__ float sm[8], ss[8];
    int w = tid >> 5, lane = tid & 31;
    if (lane == 0) sm[w] = m;
    __syncthreads();
    m = sm[0];
#pragma unroll
    for (int i = 1; i < 8; i++) m = fmaxf(m, sm[i]);

    v0.x = __expf(v0.x - m); v0.y = __expf(v0.y - m);
    v0.z = __expf(v0.z - m); v0.w = __expf(v0.w - m);
    v1.x = __expf(v1.x - m); v1.y = __expf(v1.y - m);
    v1.z = __expf(v1.z - m); v1.w = __expf(v1.w - m);

    float s = v0.x + v0.y + v0.z + v0.w + v1.x + v1.y + v1.z + v1.w;
#pragma unroll
    for (int o = 16; o; o >>= 1) s += __shfl_xor_sync(0xffffffffu, s, o);
    if (lane == 0) ss[w] = s;
    __syncthreads();
    s = ss[0] + ss[1] + ss[2] + ss[3] + ss[4] + ss[5] + ss[6] + ss[7];
    float inv = 1.0f / s;

    __half2 h0 = __floats2half2_rn(v0.x * inv, v0.y * inv);
    __half2 h1 = __floats2half2_rn(v0.z * inv, v0.w * inv);
    __half2 h2 = __floats2half2_rn(v1.x * inv, v1.y * inv);
    __half2 h3 = __floats2half2_rn(v1.z * inv, v1.w * inv);
    *(uint2*)(prow + tid * 4)         = make_uint2(*(uint32_t*)&h0, *(uint32_t*)&h1);
    *(uint2*)(prow + (tid + 256) * 4) = make_uint2(*(uint32_t*)&h2, *(uint32_t*)&h3);
}

// ---------------------------------------------------------------------------
extern "C" void kernel_launch(void* const* d_in, const int* in_sizes, int n_in,
                              void* d_out, int out_size)
{
    const float* x  = (const float*)d_in[0];
    const float* bq = (const float*)d_in[2];
    const float* bk = (const float*)d_in[4];
    const float* bv = (const float*)d_in[6];
    const float* bo = (const float*)d_in[8];
    float* out = (float*)d_out;

    __half *Xh, *Wh, *Qh, *Kh, *Vt, *P, *Y;
    float *S;
    cudaGetSymbolAddress((void**)&Xh, g_Xh);
    cudaGetSymbolAddress((void**)&Wh, g_Wh);
    cudaGetSymbolAddress((void**)&Qh, g_Qh);
    cudaGetSymbolAddress((void**)&Kh, g_Kh);
    cudaGetSymbolAddress((void**)&Vt, g_Vt);
    cudaGetSymbolAddress((void**)&S,  g_S);
    cudaGetSymbolAddress((void**)&P,  g_P);
    cudaGetSymbolAddress((void**)&Y,  g_Y);

    cudaFuncSetAttribute(mma_gemm<0, true>,  cudaFuncAttributeMaxDynamicSharedMemorySize, SMEM_TOT);
    cudaFuncSetAttribute(mma_gemm<0, false>, cudaFuncAttributeMaxDynamicSharedMemorySize, SMEM_TOT);
    cudaFuncSetAttribute(mma_gemm<1, true>,  cudaFuncAttributeMaxDynamicSharedMemorySize, SMEM_TOT);
    cudaFuncSetAttribute(mma_gemm<2, true>,  cudaFuncAttributeMaxDynamicSharedMemorySize, SMEM_TOT);

    // fp16 conversions
    f2h<<<4096, 256>>>((const float4*)x, Xh, 1024 * 1024);
    f2h<<<1024, 256>>>((const float4*)d_in[1], Wh + 0 * 1048576, 262144);
    f2h<<<1024, 256>>>((const float4*)d_in[3], Wh + 1 * 1048576, 262144);
    f2h<<<1024, 256>>>((const float4*)d_in[5], Wh + 2 * 1048576, 262144);
    f2h<<<1024, 256>>>((const float4*)d_in[7], Wh + 3 * 1048576, 262144);

    dim3 blk(256);

    // Q = Xh @ Wq^T + bq -> fp16 [4096,1024]
    mma_gemm<0, true><<<dim3(8, 32, 1), blk, SMEM_TOT>>>(
        Xh, 1024, 0, Wh, 1024, 0, bq, Qh, 1024, 0, 16, 1.f);
    // K
    mma_gemm<0, true><<<dim3(8, 32, 1), blk, SMEM_TOT>>>(
        Xh, 1024, 0, Wh + 1048576, 1024, 0, bk, Kh, 1024, 0, 16, 1.f);
    // Vt = Wv @ Xh^T + bv (bias by row=e) -> fp16 [1024,4096]
    mma_gemm<1, true><<<dim3(32, 8, 1), blk, SMEM_TOT>>>(
        Wh + 2097152, 1024, 0, Xh, 1024, 0, bv, Vt, 4096, 0, 16, 1.f);
    // S = Q @ K^T / 128 per batch -> fp32 [2,2048,2048]
    mma_gemm<0, false><<<dim3(16, 16, 2), blk, SMEM_TOT>>>(
        Qh, 1024, 2048ll * 1024, Kh, 1024, 2048ll * 1024,
        nullptr, S, 2048, 2048ll * 2048, 16, 1.f / 128.f);
    // P = softmax(S) -> fp16
    softmax2048<<<4096, 256>>>(S, P);
    // Y = P @ Vt^T per batch, shuffled -> fp16 [4096,1024]
    mma_gemm<2, true><<<dim3(8, 16, 2), blk, SMEM_TOT>>>(
        P, 2048, 2048ll * 2048, Vt, 4096, 2048,
        nullptr, Y, 1024, 2048ll * 1024, 32, 1.f);
    // out = Y @ Wo^T + bo -> fp32
    mma_gemm<0, false><<<dim3(8, 32, 1), blk, SMEM_TOT>>>(
        Y, 1024, 0, Wh + 3145728, 1024, 0, bo, out, 1024, 0, 16, 1.f);
}

// round 5
// speedup vs baseline: 6.4458x; 1.0563x over previous
#include <cuda_runtime.h>
#include <cuda_fp16.h>
#include <cstdint>

// ===========================================================================
// AxialAttention via mma.sync fp16 m16n8k16 + ldmatrix fragment loads.
//   Qh = Xh@Wqh^T+bq ; Kh = Xh@Wkh^T+bk       [4096,1024] fp16
//   Vth = Wvh@Xh^T+bv  stored [1024,4096] fp16
//   Sf  = Qh@Kh^T / 128 per batch (fp32) ; Ph = softmax rows (fp16)
//   Yh  = Ph@Vth^T per batch, shuffle-stored (reference no-transpose reshape)
//   out = Yh@Woh^T + bo (fp32)
// ===========================================================================

#define BK 64                         // fp16 elems per K-chunk (128 B per row)
#define ROW_BYTES 128
#define STG_BYTES (128 * ROW_BYTES)   // 16 KB
#define STAGES 3
#define SMEM_TOT (2 * STAGES * STG_BYTES)  // 96 KB

// scratch
__device__ __half g_Xh[4096 * 1024];
__device__ __half g_Wh[4 * 1024 * 1024];   // Wq,Wk,Wv,Wo fp16
__device__ __half g_Qh[4096 * 1024];
__device__ __half g_Kh[4096 * 1024];
__device__ __half g_Vt[1024 * 4096];
__device__ float  g_S [2ll * 2048 * 2048];
__device__ __half g_P [2ll * 2048 * 2048];
__device__ __half g_Y [4096 * 1024];

__device__ __forceinline__ void mma_f16(float* d, const uint32_t* a, const uint32_t* b) {
    asm volatile(
        "mma.sync.aligned.m16n8k16.row.col.f32.f16.f16.f32 "
        "{%0,%1,%2,%3}, {%4,%5,%6,%7}, {%8,%9}, {%0,%1,%2,%3};"
        : "+f"(d[0]), "+f"(d[1]), "+f"(d[2]), "+f"(d[3])
        : "r"(a[0]), "r"(a[1]), "r"(a[2]), "r"(a[3]), "r"(b[0]), "r"(b[1]));
}
__device__ __forceinline__ void ldsm4(uint32_t* r, uint32_t addr) {
    asm volatile("ldmatrix.sync.aligned.m8n8.x4.shared.b16 {%0,%1,%2,%3}, [%4];"
        : "=r"(r[0]), "=r"(r[1]), "=r"(r[2]), "=r"(r[3]) : "r"(addr));
}

#define CP_ASYNC(dst, src) \
    asm volatile("cp.async.cg.shared.global [%0], [%1], 16;" :: "r"(dst), \
                 "l"(__cvta_generic_to_global(src)))
#define CP_COMMIT() asm volatile("cp.async.commit_group;" ::: "memory")
#define CP_WAIT1()  asm volatile("cp.async.wait_group 1;" ::: "memory")

// ---------------------------------------------------------------------------
// 128x128 tile, 8 warps (64x32 warp tiles), 3-stage cp.async, LDSM fragments.
// MODE 0: plain store, bias by column. MODE 1: plain store, bias by row.
// MODE 2: shuffle store (reference's no-transpose reshape), no bias.
// ---------------------------------------------------------------------------
template <int MODE, bool HALF_OUT>
__global__ void __launch_bounds__(256) mma_gemm(
    const __half* __restrict__ A, int lda, long long sA,
    const __half* __restrict__ B, int ldb, long long sB,
    const float* __restrict__ bias,
    void* __restrict__ Cv, int ldC, long long sC,
    int nch, float alpha)
{
    extern __shared__ __align__(128) char smc[];

    const __half* Ab = A + blockIdx.z * sA + (long long)blockIdx.y * 128 * lda;
    const __half* Bb = B + blockIdx.z * sB + (long long)blockIdx.x * 128 * ldb;

    int tid = threadIdx.x, lane = tid & 31, wid = tid >> 5;
    int gr = lane >> 2, qc = lane & 3;
    int mw = (wid >> 2) * 64, nw = (wid & 3) * 32;

    uint32_t sA32 = (uint32_t)__cvta_generic_to_shared(smc);
    uint32_t sB32 = sA32 + STAGES * STG_BYTES;

    // ldmatrix per-lane row assignment: lanes 0-7 -> matrix0 (rows r..r+7, chunk c),
    // 8-15 -> rows+8 chunk c, 16-23 -> rows chunk c+1, 24-31 -> rows+8 chunk c+1.
    int t8 = lane & 7, half8 = (lane >> 3) & 1, cg = lane >> 4;  // cg in {0,1}
    uint32_t aRow[4], aX7[4], bRow[2], bX7[2];
#pragma unroll
    for (int mf = 0; mf < 4; mf++) {
        int r = mw + mf * 16 + half8 * 8 + t8;
        aRow[mf] = (uint32_t)r * ROW_BYTES;
        aX7[mf] = (uint32_t)(r & 7);
    }
#pragma unroll
    for (int p = 0; p < 2; p++) {
        int r = nw + p * 16 + half8 * 8 + t8;
        bRow[p] = (uint32_t)r * ROW_BYTES;
        bX7[p] = (uint32_t)(r & 7);
    }

    int lr = tid >> 3;            // cp.async: row 0..31
    int lc = tid & 7;             // 16B chunk 0..7

    float acc[4][4][4];
#pragma unroll
    for (int i = 0; i < 4; i++)
#pragma unroll
        for (int j = 0; j < 4; j++)
#pragma unroll
            for (int t = 0; t < 4; t++) acc[i][j][t] = 0.f;

    auto load_stage = [&](int ch, int st) {
        long long ko = (long long)ch * BK + lc * 8;
#pragma unroll
        for (int it = 0; it < 4; it++) {
            int r = it * 32 + lr;
            uint32_t so = (uint32_t)(st * STG_BYTES + r * ROW_BYTES +
                                     ((lc ^ (r & 7)) << 4));
            CP_ASYNC(sA32 + so, Ab + (long long)r * lda + ko);
            CP_ASYNC(sB32 + so, Bb + (long long)r * ldb + ko);
        }
    };

    load_stage(0, 0);
    CP_COMMIT();
    load_stage(1, 1);
    CP_COMMIT();

    for (int ch = 0; ch < nch; ch++) {
        CP_WAIT1();
        __syncthreads();
        if (ch + 2 < nch) load_stage(ch + 2, (ch + 2) % STAGES);
        CP_COMMIT();

        uint32_t stA = sA32 + (ch % STAGES) * STG_BYTES;
        uint32_t stB = sB32 + (ch % STAGES) * STG_BYTES;
#pragma unroll
        for (int ks = 0; ks < 4; ks++) {            // k16 steps within BK=64
            uint32_t c = (uint32_t)(ks * 2 + cg);
            uint32_t af[4][4], bb[2][4];
#pragma unroll
            for (int mf = 0; mf < 4; mf++)
                ldsm4(af[mf], stA + aRow[mf] + ((c ^ aX7[mf]) << 4));
#pragma unroll
            for (int p = 0; p < 2; p++)
                ldsm4(bb[p], stB + bRow[p] + ((c ^ bX7[p]) << 4));
            // bb[p] = { b(2p)[0], b(2p+1)[0], b(2p)[1], b(2p+1)[1] }
#pragma unroll
            for (int mf = 0; mf < 4; mf++)
#pragma unroll
                for (int nf = 0; nf < 4; nf++) {
                    uint32_t bfr[2] = { bb[nf >> 1][nf & 1], bb[nf >> 1][2 + (nf & 1)] };
                    mma_f16(acc[mf][nf], af[mf], bfr);
                }
        }
    }

    // epilogue
#pragma unroll
    for (int mf = 0; mf < 4; mf++) {
#pragma unroll
        for (int nf = 0; nf < 4; nf++) {
            int row = blockIdx.y * 128 + mw + mf * 16 + gr;
            int col = blockIdx.x * 128 + nw + nf * 8 + 2 * qc;
            float v0 = acc[mf][nf][0] * alpha;
            float v1 = acc[mf][nf][1] * alpha;
            float v2 = acc[mf][nf][2] * alpha;
            float v3 = acc[mf][nf][3] * alpha;
            if (MODE == 0 && bias) {
                float b0 = bias[col], b1 = bias[col + 1];
                v0 += b0; v1 += b1; v2 += b0; v3 += b1;
            }
            if (MODE == 1) {
                float b0 = bias[row], b1 = bias[row + 8];
                v0 += b0; v1 += b0; v2 += b1; v3 += b1;
            }
            long long o0, o1;
            if (MODE == 2) {
                int h = col >> 6, d0 = col & 63;
                o0 = (long long)(h * 128 + (row >> 4)) * 1024 + ((row & 15) << 6) + d0;
                int row2 = row + 8;
                o1 = (long long)(h * 128 + (row2 >> 4)) * 1024 + ((row2 & 15) << 6) + d0;
            } else {
                o0 = (long long)row * ldC + col;
                o1 = o0 + 8ll * ldC;
            }
            if (HALF_OUT) {
                __half* Cb = (__half*)Cv + blockIdx.z * sC;
                *(__half2*)(Cb + o0) = __floats2half2_rn(v0, v1);
                *(__half2*)(Cb + o1) = __floats2half2_rn(v2, v3);
            } else {
                float* Cb = (float*)Cv + blockIdx.z * sC;
                *(float2*)(Cb + o0) = make_float2(v0, v1);
                *(float2*)(Cb + o1) = make_float2(v2, v3);
            }
        }
    }
}

// ---------------------------------------------------------------------------
// single fused fp32->fp16 conversion pass: X (1M float4) + 4 weights (256K each)
// ---------------------------------------------------------------------------
__global__ __launch_bounds__(256) void f2h_all(
    const float4* __restrict__ x,
    const float4* __restrict__ w0, const float4* __restrict__ w1,
    const float4* __restrict__ w2, const float4* __restrict__ w3,
    __half* __restrict__ Xh, __half* __restrict__ Wh)
{
    int i = blockIdx.x * 256 + threadIdx.x;    // 0 .. 2M-1
    const float4* src;
    __half* dst;
    if (i < (1 << 20)) { src = x + i; dst = Xh + (long long)i * 4; }
    else {
        int j = i - (1 << 20);
        int w = j >> 18, off = j & ((1 << 18) - 1);
        const float4* ws[4] = {w0, w1, w2, w3};
        src = ws[w] + off;
        dst = Wh + ((long long)w << 20) + (long long)off * 4;
    }
    float4 v = *src;
    __half2 h0 = __floats2half2_rn(v.x, v.y);
    __half2 h1 = __floats2half2_rn(v.z, v.w);
    *(uint2*)dst = make_uint2(*(uint32_t*)&h0, *(uint32_t*)&h1);
}

// ---------------------------------------------------------------------------
// row softmax on fp32 scores (2048 wide), fp16 output
// ---------------------------------------------------------------------------
__global__ __launch_bounds__(256) void softmax2048(const float* __restrict__ S,
                                                   __half* __restrict__ P)
{
    const float* row = S + (long long)blockIdx.x * 2048;
    __half* prow = P + (long long)blockIdx.x * 2048;
    int tid = threadIdx.x;
    float4 v0 = ((const float4*)row)[tid];
    float4 v1 = ((const float4*)row)[tid + 256];

    float m = fmaxf(fmaxf(fmaxf(v0.x, v0.y), fmaxf(v0.z, v0.w)),
                    fmaxf(fmaxf(v1.x, v1.y), fmaxf(v1.z, v1.w)));
#pragma unroll
    for (int o = 16; o; o >>= 1) m = fmaxf(m, __shfl_xor_sync(0xffffffffu, m, o));

    __shared__ float sm[8], ss[8];
    int w = tid >> 5, lane = tid & 31;
    if (lane == 0) sm[w] = m;
    __syncthreads();
    m = sm[0];
#pragma unroll
    for (int i = 1; i < 8; i++) m = fmaxf(m, sm[i]);

    v0.x = __expf(v0.x - m); v0.y = __expf(v0.y - m);
    v0.z = __expf(v0.z - m); v0.w = __expf(v0.w - m);
    v1.x = __expf(v1.x - m); v1.y = __expf(v1.y - m);
    v1.z = __expf(v1.z - m); v1.w = __expf(v1.w - m);

    float s = v0.x + v0.y + v0.z + v0.w + v1.x + v1.y + v1.z + v1.w;
#pragma unroll
    for (int o = 16; o; o >>= 1) s += __shfl_xor_sync(0xffffffffu, s, o);
    if (lane == 0) ss[w] = s;
    __syncthreads();
    s = ss[0] + ss[1] + ss[2] + ss[3] + ss[4] + ss[5] + ss[6] + ss[7];
    float inv = 1.0f / s;

    __half2 h0 = __floats2half2_rn(v0.x * inv, v0.y * inv);
    __half2 h1 = __floats2half2_rn(v0.z * inv, v0.w * inv);
    __half2 h2 = __floats2half2_rn(v1.x * inv, v1.y * inv);
    __half2 h3 = __floats2half2_rn(v1.z * inv, v1.w * inv);
    *(uint2*)(prow + tid * 4)         = make_uint2(*(uint32_t*)&h0, *(uint32_t*)&h1);
    *(uint2*)(prow + (tid + 256) * 4) = make_uint2(*(uint32_t*)&h2, *(uint32_t*)&h3);
}

// ---------------------------------------------------------------------------
extern "C" void kernel_launch(void* const* d_in, const int* in_sizes, int n_in,
                              void* d_out, int out_size)
{
    const float* x  = (const float*)d_in[0];
    const float* bq = (const float*)d_in[2];
    const float* bk = (const float*)d_in[4];
    const float* bv = (const float*)d_in[6];
    const float* bo = (const float*)d_in[8];
    float* out = (float*)d_out;

    __half *Xh, *Wh, *Qh, *Kh, *Vt, *P, *Y;
    float *S;
    cudaGetSymbolAddress((void**)&Xh, g_Xh);
    cudaGetSymbolAddress((void**)&Wh, g_Wh);
    cudaGetSymbolAddress((void**)&Qh, g_Qh);
    cudaGetSymbolAddress((void**)&Kh, g_Kh);
    cudaGetSymbolAddress((void**)&Vt, g_Vt);
    cudaGetSymbolAddress((void**)&S,  g_S);
    cudaGetSymbolAddress((void**)&P,  g_P);
    cudaGetSymbolAddress((void**)&Y,  g_Y);

    cudaFuncSetAttribute(mma_gemm<0, true>,  cudaFuncAttributeMaxDynamicSharedMemorySize, SMEM_TOT);
    cudaFuncSetAttribute(mma_gemm<0, false>, cudaFuncAttributeMaxDynamicSharedMemorySize, SMEM_TOT);
    cudaFuncSetAttribute(mma_gemm<1, true>,  cudaFuncAttributeMaxDynamicSharedMemorySize, SMEM_TOT);
    cudaFuncSetAttribute(mma_gemm<2, true>,  cudaFuncAttributeMaxDynamicSharedMemorySize, SMEM_TOT);

    // fused fp16 conversion (2M float4 total)
    f2h_all<<<8192, 256>>>((const float4*)x,
                           (const float4*)d_in[1], (const float4*)d_in[3],
                           (const float4*)d_in[5], (const float4*)d_in[7],
                           Xh, Wh);

    dim3 blk(256);

    // Q = Xh @ Wq^T + bq -> fp16 [4096,1024]
    mma_gemm<0, true><<<dim3(8, 32, 1), blk, SMEM_TOT>>>(
        Xh, 1024, 0, Wh, 1024, 0, bq, Qh, 1024, 0, 16, 1.f);
    // K
    mma_gemm<0, true><<<dim3(8, 32, 1), blk, SMEM_TOT>>>(
        Xh, 1024, 0, Wh + 1048576, 1024, 0, bk, Kh, 1024, 0, 16, 1.f);
    // Vt = Wv @ Xh^T + bv (bias by row=e) -> fp16 [1024,4096]
    mma_gemm<1, true><<<dim3(32, 8, 1), blk, SMEM_TOT>>>(
        Wh + 2097152, 1024, 0, Xh, 1024, 0, bv, Vt, 4096, 0, 16, 1.f);
    // S = Q @ K^T / 128 per batch -> fp32 [2,2048,2048]
    mma_gemm<0, false><<<dim3(16, 16, 2), blk, SMEM_TOT>>>(
        Qh, 1024, 2048ll * 1024, Kh, 1024, 2048ll * 1024,
        nullptr, S, 2048, 2048ll * 2048, 16, 1.f / 128.f);
    // P = softmax(S) -> fp16
    softmax2048<<<4096, 256>>>(S, P);
    // Y = P @ Vt^T per batch, shuffled -> fp16 [4096,1024]
    mma_gemm<2, true><<<dim3(8, 16, 2), blk, SMEM_TOT>>>(
        P, 2048, 2048ll * 2048, Vt, 4096, 2048,
        nullptr, Y, 1024, 2048ll * 1024, 32, 1.f);
    // out = Y @ Wo^T + bo -> fp32
    mma_gemm<0, false><<<dim3(8, 32, 1), blk, SMEM_TOT>>>(
        Y, 1024, 0, Wh + 3145728, 1024, 0, bo, out, 1024, 0, 16, 1.f);
}